// round 11
// baseline (speedup 1.0000x reference)
#include <cuda_runtime.h>
#include <cuda_fp16.h>
#include <cstdint>

// Problem constants (fixed shapes)
#define BATCH   2
#define NLIGHT  8
#define HDIM    128
#define D0      128
#define D1      128
#define D2      128
#define NCAM    3
#define NNZ     2097152              // 2^21
#define XYZ     (D0*D1*D2)           // 2^21
#define ROWS_T  (D0*D1)              // 16384
#define BN      (BATCH*NLIGHT)       // 16
#define OUTSZ   (BATCH*NLIGHT*NCAM*D0*D1)  // 786432
#define NROWCAM (NCAM*ROWS_T)        // 49152
#define CAP     256                  // bucket capacity (Poisson(128): >11 sigma)

// exponnorm params
#define P_K     1.790987517302874f
#define P_LOC   -0.08208043639065216f
#define P_SCALE 0.05720079131427573f

// ---------------- bit-cast helpers ----------------
__device__ __forceinline__ unsigned h2_to_u(half2 h) {
    __half2_raw r = *reinterpret_cast<__half2_raw*>(&h);
    return (unsigned)r.x | ((unsigned)r.y << 16);
}
__device__ __forceinline__ half2 u_to_h2(unsigned u) {
    __half2_raw r;
    r.x = (unsigned short)(u & 0xFFFFu);
    r.y = (unsigned short)(u >> 16);
    return *reinterpret_cast<half2*>(&r);
}

// ---------------- device scratch (static, no allocations) ----------------
__device__ uint4  g_lh[ROWS_T];             // light[xz] as 8 x fp16, 256KB
__device__ float2 g_d2[XYZ];                // density transposed, 16MB
__device__ float  g_acc[NCAM*ROWS_T*BN];    // result accumulator, 3MB
__device__ int    g_cnt[NROWCAM];           // bucket fill counters, 192KB
__device__ uint2  g_bucket[NROWCAM*CAP];    // {v.f32, col}, 101MB

// ---------------- threefry2x32 ----------------
__host__ __device__ __forceinline__ unsigned rotl32(unsigned x, int r) {
    return (x << r) | (x >> (32 - r));
}

__host__ __device__ __forceinline__ void threefry2x32(
    unsigned k0, unsigned k1, unsigned x0, unsigned x1,
    unsigned* o0, unsigned* o1)
{
    unsigned ks0 = k0, ks1 = k1, ks2 = k0 ^ k1 ^ 0x1BD11BDAu;
    x0 += ks0; x1 += ks1;
#define TF_R4(a,b,c,d) \
    x0 += x1; x1 = rotl32(x1,a); x1 ^= x0; \
    x0 += x1; x1 = rotl32(x1,b); x1 ^= x0; \
    x0 += x1; x1 = rotl32(x1,c); x1 ^= x0; \
    x0 += x1; x1 = rotl32(x1,d); x1 ^= x0;
    TF_R4(13,15,26,6);  x0 += ks1; x1 += ks2 + 1u;
    TF_R4(17,29,16,24); x0 += ks2; x1 += ks0 + 2u;
    TF_R4(13,15,26,6);  x0 += ks0; x1 += ks1 + 3u;
    TF_R4(17,29,16,24); x0 += ks1; x1 += ks2 + 4u;
    TF_R4(13,15,26,6);  x0 += ks2; x1 += ks0 + 5u;
#undef TF_R4
    *o0 = x0; *o1 = x1;
}

// Partitionable threefry random_bits: element i -> counter (0, i), out0 ^ out1.
__device__ __forceinline__ unsigned tf_bits_part(unsigned k0, unsigned k1, unsigned i) {
    unsigned o0, o1;
    threefry2x32(k0, k1, 0u, i, &o0, &o1);
    return o0 ^ o1;
}

// ---------------- kernels ----------------

// Fused: each block redundantly computes w = sigmoid(lp)/||sigmoid(lp)||,
// then light[xz][n] = sum_h light_info[h][xz] * w[n][h], stored as 8 x fp16.
__global__ void __launch_bounds__(256) k_light(
    const float* __restrict__ lp, const float* __restrict__ li)
{
    __shared__ float w[NLIGHT*HDIM];
    __shared__ float red[8];
    int t = threadIdx.x;

    float sumsq = 0.0f;
    #pragma unroll
    for (int j = 0; j < 4; j++) {
        int i = t + j * 256;
        float s = 1.0f / (1.0f + expf(-lp[i]));
        w[i] = s;
        sumsq += s * s;
    }
    #pragma unroll
    for (int off = 16; off > 0; off >>= 1)
        sumsq += __shfl_xor_sync(0xFFFFFFFFu, sumsq, off);
    if ((t & 31) == 0) red[t >> 5] = sumsq;
    __syncthreads();
    float inv;
    {
        float tot = red[0];
        #pragma unroll
        for (int k = 1; k < 8; k++) tot += red[k];
        inv = rsqrtf(tot);
    }
    __syncthreads();
    #pragma unroll
    for (int j = 0; j < 4; j++) w[t + j * 256] *= inv;
    __syncthreads();

    int xz = blockIdx.x * 256 + t;
    float acc[NLIGHT];
    #pragma unroll
    for (int n = 0; n < NLIGHT; n++) acc[n] = 0.0f;
    #pragma unroll 4
    for (int h = 0; h < HDIM; h++) {
        float v = li[h * ROWS_T + xz];
        #pragma unroll
        for (int n = 0; n < NLIGHT; n++)
            acc[n] = fmaf(v, w[n * HDIM + h], acc[n]);
    }
    uint4 packed;
    packed.x = h2_to_u(__floats2half2_rn(acc[0], acc[1]));
    packed.y = h2_to_u(__floats2half2_rn(acc[2], acc[3]));
    packed.z = h2_to_u(__floats2half2_rn(acc[4], acc[5]));
    packed.w = h2_to_u(__floats2half2_rn(acc[6], acc[7]));
    g_lh[xz] = packed;
}

// density transpose (blocks 0..2047) + zero bucket counters (blocks 2048..2095)
__global__ void __launch_bounds__(256) k_d2z(const float* __restrict__ dv) {
    int bid = blockIdx.x;
    if (bid >= 2048) {
        int i = (bid - 2048) * 256 + threadIdx.x;   // 48*256 = 12288 int4 = 49152
        reinterpret_cast<int4*>(g_cnt)[i] = make_int4(0, 0, 0, 0);
        return;
    }
    int i = (bid * 256 + threadIdx.x) * 4;
    float4 a = *reinterpret_cast<const float4*>(dv + i);
    float4 b = *reinterpret_cast<const float4*>(dv + XYZ + i);
    float4* o = reinterpret_cast<float4*>(g_d2 + i);
    o[0] = make_float4(a.x, b.x, a.y, b.y);
    o[1] = make_float4(a.z, b.z, a.w, b.w);
}

// phase 1: per nnz, append {v, col} to bucket[cam][row].
// 2 scattered ops per nnz (counter atomic + 8B store); 8 nnz per thread for ILP.
__global__ void __launch_bounds__(256) k_phase1(
    const int* __restrict__ rows, const int* __restrict__ cols,
    const float* __restrict__ vals)
{
    int t = blockIdx.x * 256 + threadIdx.x;     // 0 .. 3*NNZ/8-1
    int cam = t >> 18;                           // NNZ/8 = 2^18 per camera

    const int4*   r4 = reinterpret_cast<const int4*>(rows) + t * 2;
    const int4*   c4 = reinterpret_cast<const int4*>(cols) + t * 2;
    const float4* v4 = reinterpret_cast<const float4*>(vals) + t * 2;
    int4   ra = __ldcs(r4),   rb = __ldcs(r4 + 1);
    int4   ca = __ldcs(c4),   cb = __ldcs(c4 + 1);
    float4 va = __ldcs(v4),   vb = __ldcs(v4 + 1);

    int rr[8]   = {ra.x, ra.y, ra.z, ra.w, rb.x, rb.y, rb.z, rb.w};
    int cc[8]   = {ca.x, ca.y, ca.z, ca.w, cb.x, cb.y, cb.z, cb.w};
    float vv[8] = {va.x, va.y, va.z, va.w, vb.x, vb.y, vb.z, vb.w};

    // 8 independent counter atomics in flight
    int slot[8];
    #pragma unroll
    for (int j = 0; j < 8; j++) {
        int id = (cam << 14) + rr[j];
        slot[j] = atomicAdd(&g_cnt[id], 1) & (CAP - 1);   // mask: memory safety
    }

    #pragma unroll
    for (int j = 0; j < 8; j++) {
        int id = (cam << 14) + rr[j];
        uint2 rec = make_uint2(__float_as_uint(vv[j]), (unsigned)cc[j]);
        __stcs(&g_bucket[id * CAP + slot[j]], rec);       // evict-first stream
    }
}

// phase 2: one warp per (cam,row). Stanza-4 prefetch (records -> d2+lh gathers
// batched for MLP), second half only when cnt > 128. launch_bounds(256,3)
// keeps ~85 regs available so ptxas doesn't serialize the prefetch.
__global__ void __launch_bounds__(256, 3) k_phase2() {
    int gw = (blockIdx.x * 256 + threadIdx.x) >> 5;   // 0 .. NROWCAM-1
    int lane = threadIdx.x & 31;

    int cnt = g_cnt[gw];
    if (cnt > CAP) cnt = CAP;
    int nst = (cnt + 31) >> 5;                         // active stanzas, 0..8
    const uint2* bucket = g_bucket + gw * CAP;

    float aa[8], bb[8];
    #pragma unroll
    for (int k = 0; k < 8; k++) { aa[k] = 0.0f; bb[k] = 0.0f; }

    #pragma unroll
    for (int half = 0; half < 2; half++) {
        if (half == 1 && nst <= 4) break;              // warp-uniform branch
        int base = half * 4;

        // batched record loads (independent)
        uint2 e[4];
        #pragma unroll
        for (int k = 0; k < 4; k++) {
            int s = lane + ((base + k) << 5);
            e[k] = (s < cnt) ? __ldcs(&bucket[s]) : make_uint2(0u, 0u);
        }
        // batched d2 gathers (L2) + lh gathers (L1-resident 256KB table)
        float2 d[4];
        uint4  l[4];
        #pragma unroll
        for (int k = 0; k < 4; k++) d[k] = __ldcg(&g_d2[e[k].y]);
        #pragma unroll
        for (int k = 0; k < 4; k++) {
            unsigned col = e[k].y;
            unsigned xz = ((col >> 14) << 7) | (col & 127u);
            l[k] = __ldg(&g_lh[xz]);
        }

        #pragma unroll
        for (int k = 0; k < 4; k++) {
            if (base + k < nst) {                      // warp-uniform per stanza
                float v = __uint_as_float(e[k].x);
                float a = v * d[k].x;
                float b = v * d[k].y;
                float2 l01 = __half22float2(u_to_h2(l[k].x));
                float2 l23 = __half22float2(u_to_h2(l[k].y));
                float2 l45 = __half22float2(u_to_h2(l[k].z));
                float2 l67 = __half22float2(u_to_h2(l[k].w));
                float lv[8] = {l01.x, l01.y, l23.x, l23.y,
                               l45.x, l45.y, l67.x, l67.y};
                #pragma unroll
                for (int j = 0; j < 8; j++) {
                    aa[j] = fmaf(a, lv[j], aa[j]);
                    bb[j] = fmaf(b, lv[j], bb[j]);
                }
            }
        }
    }

    // butterfly reduce each of the 16 accumulators across the warp
    #pragma unroll
    for (int k = 0; k < 8; k++) {
        #pragma unroll
        for (int off = 16; off > 0; off >>= 1) {
            aa[k] += __shfl_xor_sync(0xFFFFFFFFu, aa[k], off);
            bb[k] += __shfl_xor_sync(0xFFFFFFFFu, bb[k], off);
        }
    }

    if (lane == 0) {
        float4* o = reinterpret_cast<float4*>(g_acc + gw * 16);
        o[0] = make_float4(aa[0], aa[1], aa[2], aa[3]);
        o[1] = make_float4(aa[4], aa[5], aa[6], aa[7]);
        o[2] = make_float4(bb[0], bb[1], bb[2], bb[3]);
        o[3] = make_float4(bb[4], bb[5], bb[6], bb[7]);
    }
}

// finalize: out[b,n,c,X,Y] = acc[c][X*128+Y][b*8+n] * (1 + noise[i])
__global__ void __launch_bounds__(256) k_final(
    float* __restrict__ out,
    unsigned kn0, unsigned kn1, unsigned ke0, unsigned ke1)
{
    int i = blockIdx.x * 256 + threadIdx.x;   // 0 .. OUTSZ-1
    int r  = i & (ROWS_T - 1);
    int t  = i >> 14;          // bn*3 + c
    int bn = t / NCAM;
    int c  = t - bn * NCAM;

    float x = g_acc[((((unsigned)c << 14) + (unsigned)r) << 4) + (unsigned)bn];

    // normal(kn): uniform in [nextafter(-1,0), 1), z = sqrt(2)*erfinv(u)
    unsigned nb = tf_bits_part(kn0, kn1, (unsigned)i);
    float fn = __uint_as_float((nb >> 9) | 0x3f800000u) - 1.0f;
    const float lo = -0.99999994f;                 // nextafterf(-1,0)
    float u = fmaxf(lo, fn * (1.0f - lo) + lo);
    float nrm = 1.41421356237309515f * erfinvf(u);

    // exponential(ke): u in [0,1), e = -log1p(-u)
    unsigned eb = tf_bits_part(ke0, ke1, (unsigned)i);
    float fe = __uint_as_float((eb >> 9) | 0x3f800000u) - 1.0f;
    float ex = -log1pf(-fe);

    float noise = (P_LOC + P_SCALE * nrm) + (P_K * P_SCALE) * ex;
    out[i] = x + x * noise;
}

// ---------------- launch ----------------
extern "C" void kernel_launch(void* const* d_in, const int* in_sizes, int n_in,
                              void* d_out, int out_size)
{
    const float* density    = (const float*)d_in[0];  // (2,128,128,128)
    const float* light_pat  = (const float*)d_in[1];  // (8,128)
    const float* light_info = (const float*)d_in[2];  // (128,128,128)
    const int*   ray_rows   = (const int*)d_in[3];    // (3, NNZ)
    const int*   ray_cols   = (const int*)d_in[4];    // (3, NNZ)
    const float* ray_vals   = (const float*)d_in[5];  // (3, NNZ)
    float* out = (float*)d_out;

    // jax.random.key(42); partitionable split(key,2): subkey_i = threefry(k,(0,i))
    unsigned kn0, kn1, ke0, ke1;
    threefry2x32(0u, 42u, 0u, 0u, &kn0, &kn1);   // subkey 0 -> normal
    threefry2x32(0u, 42u, 0u, 1u, &ke0, &ke1);   // subkey 1 -> exponential

    k_light<<<ROWS_T/256, 256>>>(light_pat, light_info);
    k_d2z<<<2048 + 48, 256>>>(density);
    k_phase1<<<(NCAM*NNZ/8)/256, 256>>>(ray_rows, ray_cols, ray_vals);
    k_phase2<<<(NROWCAM*32)/256, 256>>>();
    k_final<<<OUTSZ/256, 256>>>(out, kn0, kn1, ke0, ke1);
}

// round 12
// speedup vs baseline: 1.0662x; 1.0662x over previous
#include <cuda_runtime.h>
#include <cuda_fp16.h>
#include <cstdint>

// Problem constants (fixed shapes)
#define BATCH   2
#define NLIGHT  8
#define HDIM    128
#define D0      128
#define D1      128
#define D2      128
#define NCAM    3
#define NNZ     2097152              // 2^21
#define XYZ     (D0*D1*D2)           // 2^21
#define ROWS_T  (D0*D1)              // 16384
#define BN      (BATCH*NLIGHT)       // 16
#define OUTSZ   (BATCH*NLIGHT*NCAM*D0*D1)  // 786432

// exponnorm params
#define P_K     1.790987517302874f
#define P_LOC   -0.08208043639065216f
#define P_SCALE 0.05720079131427573f

// ---------------- bit-cast helpers ----------------
__device__ __forceinline__ unsigned h2_to_u(half2 h) {
    __half2_raw r = *reinterpret_cast<__half2_raw*>(&h);
    return (unsigned)r.x | ((unsigned)r.y << 16);
}
__device__ __forceinline__ half2 u_to_h2(unsigned u) {
    __half2_raw r;
    r.x = (unsigned short)(u & 0xFFFFu);
    r.y = (unsigned short)(u >> 16);
    return *reinterpret_cast<half2*>(&r);
}

// ---------------- device scratch (static, no allocations) ----------------
__device__ uint4    g_lh[ROWS_T];            // light[xz] as 8 x fp16, 256KB
__device__ unsigned g_d2h[XYZ];              // density (d0,d1) as half2, 8MB
__device__ float    g_acc[NCAM*ROWS_T*BN];   // accumulator [c][row][bn], 3MB

// ---------------- threefry2x32 ----------------
__host__ __device__ __forceinline__ unsigned rotl32(unsigned x, int r) {
    return (x << r) | (x >> (32 - r));
}

__host__ __device__ __forceinline__ void threefry2x32(
    unsigned k0, unsigned k1, unsigned x0, unsigned x1,
    unsigned* o0, unsigned* o1)
{
    unsigned ks0 = k0, ks1 = k1, ks2 = k0 ^ k1 ^ 0x1BD11BDAu;
    x0 += ks0; x1 += ks1;
#define TF_R4(a,b,c,d) \
    x0 += x1; x1 = rotl32(x1,a); x1 ^= x0; \
    x0 += x1; x1 = rotl32(x1,b); x1 ^= x0; \
    x0 += x1; x1 = rotl32(x1,c); x1 ^= x0; \
    x0 += x1; x1 = rotl32(x1,d); x1 ^= x0;
    TF_R4(13,15,26,6);  x0 += ks1; x1 += ks2 + 1u;
    TF_R4(17,29,16,24); x0 += ks2; x1 += ks0 + 2u;
    TF_R4(13,15,26,6);  x0 += ks0; x1 += ks1 + 3u;
    TF_R4(17,29,16,24); x0 += ks1; x1 += ks2 + 4u;
    TF_R4(13,15,26,6);  x0 += ks2; x1 += ks0 + 5u;
#undef TF_R4
    *o0 = x0; *o1 = x1;
}

// Partitionable threefry random_bits: element i -> counter (0, i), out0 ^ out1.
__device__ __forceinline__ unsigned tf_bits_part(unsigned k0, unsigned k1, unsigned i) {
    unsigned o0, o1;
    threefry2x32(k0, k1, 0u, i, &o0, &o1);
    return o0 ^ o1;
}

// ---------------- kernels ----------------

// Fused: each block redundantly computes w = sigmoid(lp)/||sigmoid(lp)||,
// then light[xz][n] = sum_h light_info[h][xz] * w[n][h], stored as 8 x fp16.
__global__ void __launch_bounds__(256) k_light(
    const float* __restrict__ lp, const float* __restrict__ li)
{
    __shared__ float w[NLIGHT*HDIM];
    __shared__ float red[8];
    int t = threadIdx.x;

    float sumsq = 0.0f;
    #pragma unroll
    for (int j = 0; j < 4; j++) {
        int i = t + j * 256;
        float s = 1.0f / (1.0f + expf(-lp[i]));
        w[i] = s;
        sumsq += s * s;
    }
    #pragma unroll
    for (int off = 16; off > 0; off >>= 1)
        sumsq += __shfl_xor_sync(0xFFFFFFFFu, sumsq, off);
    if ((t & 31) == 0) red[t >> 5] = sumsq;
    __syncthreads();
    float inv;
    {
        float tot = red[0];
        #pragma unroll
        for (int k = 1; k < 8; k++) tot += red[k];
        inv = rsqrtf(tot);
    }
    __syncthreads();
    #pragma unroll
    for (int j = 0; j < 4; j++) w[t + j * 256] *= inv;
    __syncthreads();

    int xz = blockIdx.x * 256 + t;
    float acc[NLIGHT];
    #pragma unroll
    for (int n = 0; n < NLIGHT; n++) acc[n] = 0.0f;
    #pragma unroll 4
    for (int h = 0; h < HDIM; h++) {
        float v = li[h * ROWS_T + xz];
        #pragma unroll
        for (int n = 0; n < NLIGHT; n++)
            acc[n] = fmaf(v, w[n * HDIM + h], acc[n]);
    }
    uint4 packed;
    packed.x = h2_to_u(__floats2half2_rn(acc[0], acc[1]));
    packed.y = h2_to_u(__floats2half2_rn(acc[2], acc[3]));
    packed.z = h2_to_u(__floats2half2_rn(acc[4], acc[5]));
    packed.w = h2_to_u(__floats2half2_rn(acc[6], acc[7]));
    g_lh[xz] = packed;
}

// density transpose -> packed half2: d2h[col] = h2(dv[0][col], dv[1][col])
__global__ void __launch_bounds__(256) k_d2(const float* __restrict__ dv) {
    int i = (blockIdx.x * 256 + threadIdx.x) * 4;
    float4 a = *reinterpret_cast<const float4*>(dv + i);
    float4 b = *reinterpret_cast<const float4*>(dv + XYZ + i);
    uint4 o;
    o.x = h2_to_u(__floats2half2_rn(a.x, b.x));
    o.y = h2_to_u(__floats2half2_rn(a.y, b.y));
    o.z = h2_to_u(__floats2half2_rn(a.z, b.z));
    o.w = h2_to_u(__floats2half2_rn(a.w, b.w));
    *reinterpret_cast<uint4*>(g_d2h + i) = o;
}

// zero accumulator (float4)
__global__ void __launch_bounds__(256) k_zero() {
    int i = blockIdx.x * 256 + threadIdx.x;
    reinterpret_cast<float4*>(g_acc)[i] = make_float4(0.f, 0.f, 0.f, 0.f);
}

__device__ __forceinline__ void red_v4(float* p, float a, float b, float c, float d) {
    unsigned long long gp = __cvta_generic_to_global((void*)p);
    asm volatile("red.global.add.v4.f32 [%0], {%1,%2,%3,%4};"
                 :: "l"(gp), "f"(a), "f"(b), "f"(c), "f"(d) : "memory");
}

// scatter: one thread per 4 consecutive nnz (same camera; NNZ % 4 == 0)
__global__ void __launch_bounds__(256) k_scatter(
    const int* __restrict__ rows, const int* __restrict__ cols,
    const float* __restrict__ vals)
{
    int t = blockIdx.x * 256 + threadIdx.x;     // 0 .. 3*NNZ/4-1
    int cam = t >> 19;                           // NNZ/4 = 2^19 per camera

    // read-once streams: evict-first so they don't displace the gather tables
    int4   r4 = __ldcs(reinterpret_cast<const int4*>(rows) + t);
    int4   c4 = __ldcs(reinterpret_cast<const int4*>(cols) + t);
    float4 v4 = __ldcs(reinterpret_cast<const float4*>(vals) + t);

    int rr[4] = {r4.x, r4.y, r4.z, r4.w};
    int cc[4] = {c4.x, c4.y, c4.z, c4.w};
    float vv[4] = {v4.x, v4.y, v4.z, v4.w};

    // d2 gather: L2-only (.cg) — 8MB table, now fully L2-resident
    unsigned dh[4];
    #pragma unroll
    for (int j = 0; j < 4; j++) dh[j] = __ldcg(&g_d2h[cc[j]]);

    // light gather: L1-cached (.ca) — 256KB table, mostly L1-resident
    uint4 l[4];
    #pragma unroll
    for (int j = 0; j < 4; j++) {
        int xz = ((cc[j] >> 14) << 7) | (cc[j] & 127);
        l[j] = __ldg(&g_lh[xz]);
    }

    float* cbase = g_acc + ((unsigned)cam << 18);   // cam * 16384 * 16
    #pragma unroll
    for (int j = 0; j < 4; j++) {
        float2 d = __half22float2(u_to_h2(dh[j]));
        float a = vv[j] * d.x;
        float b = vv[j] * d.y;
        float2 l01 = __half22float2(u_to_h2(l[j].x));
        float2 l23 = __half22float2(u_to_h2(l[j].y));
        float2 l45 = __half22float2(u_to_h2(l[j].z));
        float2 l67 = __half22float2(u_to_h2(l[j].w));
        float* base = cbase + ((unsigned)rr[j] << 4);
        red_v4(base + 0,  a*l01.x, a*l01.y, a*l23.x, a*l23.y);
        red_v4(base + 4,  a*l45.x, a*l45.y, a*l67.x, a*l67.y);
        red_v4(base + 8,  b*l01.x, b*l01.y, b*l23.x, b*l23.y);
        red_v4(base + 12, b*l45.x, b*l45.y, b*l67.x, b*l67.y);
    }
}

// finalize: out[b,n,c,X,Y] = acc[c][X*128+Y][b*8+n] * (1 + noise[i])
__global__ void __launch_bounds__(256) k_final(
    float* __restrict__ out,
    unsigned kn0, unsigned kn1, unsigned ke0, unsigned ke1)
{
    int i = blockIdx.x * 256 + threadIdx.x;   // 0 .. OUTSZ-1
    int r  = i & (ROWS_T - 1);
    int t  = i >> 14;          // bn*3 + c
    int bn = t / NCAM;
    int c  = t - bn * NCAM;

    float x = g_acc[((((unsigned)c << 14) + (unsigned)r) << 4) + (unsigned)bn];

    // normal(kn): uniform in [nextafter(-1,0), 1), z = sqrt(2)*erfinv(u)
    unsigned nb = tf_bits_part(kn0, kn1, (unsigned)i);
    float fn = __uint_as_float((nb >> 9) | 0x3f800000u) - 1.0f;
    const float lo = -0.99999994f;                 // nextafterf(-1,0)
    float u = fmaxf(lo, fn * (1.0f - lo) + lo);
    float nrm = 1.41421356237309515f * erfinvf(u);

    // exponential(ke): u in [0,1), e = -log1p(-u)
    unsigned eb = tf_bits_part(ke0, ke1, (unsigned)i);
    float fe = __uint_as_float((eb >> 9) | 0x3f800000u) - 1.0f;
    float ex = -log1pf(-fe);

    float noise = (P_LOC + P_SCALE * nrm) + (P_K * P_SCALE) * ex;
    out[i] = x + x * noise;
}

// ---------------- launch ----------------
extern "C" void kernel_launch(void* const* d_in, const int* in_sizes, int n_in,
                              void* d_out, int out_size)
{
    const float* density    = (const float*)d_in[0];  // (2,128,128,128)
    const float* light_pat  = (const float*)d_in[1];  // (8,128)
    const float* light_info = (const float*)d_in[2];  // (128,128,128)
    const int*   ray_rows   = (const int*)d_in[3];    // (3, NNZ)
    const int*   ray_cols   = (const int*)d_in[4];    // (3, NNZ)
    const float* ray_vals   = (const float*)d_in[5];  // (3, NNZ)
    float* out = (float*)d_out;

    // jax.random.key(42); partitionable split(key,2): subkey_i = threefry(k,(0,i))
    unsigned kn0, kn1, ke0, ke1;
    threefry2x32(0u, 42u, 0u, 0u, &kn0, &kn1);   // subkey 0 -> normal
    threefry2x32(0u, 42u, 0u, 1u, &ke0, &ke1);   // subkey 1 -> exponential

    k_light<<<ROWS_T/256, 256>>>(light_pat, light_info);
    k_d2<<<XYZ/(256*4), 256>>>(density);
    k_zero<<<(NCAM*ROWS_T*BN/4)/256, 256>>>();
    k_scatter<<<(NCAM*NNZ/4)/256, 256>>>(ray_rows, ray_cols, ray_vals);
    k_final<<<OUTSZ/256, 256>>>(out, kn0, kn1, ke0, ke1);
}

// round 15
// speedup vs baseline: 1.0786x; 1.0116x over previous
#include <cuda_runtime.h>
#include <cuda_fp16.h>
#include <cstdint>

// Problem constants (fixed shapes)
#define BATCH   2
#define NLIGHT  8
#define HDIM    128
#define D0      128
#define D1      128
#define D2      128
#define NCAM    3
#define NNZ     2097152              // 2^21
#define XYZ     (D0*D1*D2)           // 2^21
#define ROWS_T  (D0*D1)              // 16384
#define BN      (BATCH*NLIGHT)       // 16
#define OUTSZ   (BATCH*NLIGHT*NCAM*D0*D1)  // 786432

// exponnorm params
#define P_K     1.790987517302874f
#define P_LOC   -0.08208043639065216f
#define P_SCALE 0.05720079131427573f

// ---------------- bit-cast helpers ----------------
__device__ __forceinline__ unsigned h2_to_u(half2 h) {
    __half2_raw r = *reinterpret_cast<__half2_raw*>(&h);
    return (unsigned)r.x | ((unsigned)r.y << 16);
}
__device__ __forceinline__ half2 u_to_h2(unsigned u) {
    __half2_raw r;
    r.x = (unsigned short)(u & 0xFFFFu);
    r.y = (unsigned short)(u >> 16);
    return *reinterpret_cast<half2*>(&r);
}

// ---------------- device scratch (static, no allocations) ----------------
__device__ uint4    g_lh[ROWS_T];            // light[xz] as 8 x fp16, 256KB
__device__ unsigned g_d2h[XYZ];              // density (d0,d1) as half2, 8MB
__device__ float    g_acc[NCAM*ROWS_T*BN];   // accumulator [c][row][bn], 3MB

// ---------------- threefry2x32 ----------------
__host__ __device__ __forceinline__ unsigned rotl32(unsigned x, int r) {
    return (x << r) | (x >> (32 - r));
}

__host__ __device__ __forceinline__ void threefry2x32(
    unsigned k0, unsigned k1, unsigned x0, unsigned x1,
    unsigned* o0, unsigned* o1)
{
    unsigned ks0 = k0, ks1 = k1, ks2 = k0 ^ k1 ^ 0x1BD11BDAu;
    x0 += ks0; x1 += ks1;
#define TF_R4(a,b,c,d) \
    x0 += x1; x1 = rotl32(x1,a); x1 ^= x0; \
    x0 += x1; x1 = rotl32(x1,b); x1 ^= x0; \
    x0 += x1; x1 = rotl32(x1,c); x1 ^= x0; \
    x0 += x1; x1 = rotl32(x1,d); x1 ^= x0;
    TF_R4(13,15,26,6);  x0 += ks1; x1 += ks2 + 1u;
    TF_R4(17,29,16,24); x0 += ks2; x1 += ks0 + 2u;
    TF_R4(13,15,26,6);  x0 += ks0; x1 += ks1 + 3u;
    TF_R4(17,29,16,24); x0 += ks1; x1 += ks2 + 4u;
    TF_R4(13,15,26,6);  x0 += ks2; x1 += ks0 + 5u;
#undef TF_R4
    *o0 = x0; *o1 = x1;
}

// Partitionable threefry random_bits: element i -> counter (0, i), out0 ^ out1.
__device__ __forceinline__ unsigned tf_bits_part(unsigned k0, unsigned k1, unsigned i) {
    unsigned o0, o1;
    threefry2x32(k0, k1, 0u, i, &o0, &o1);
    return o0 ^ o1;
}

// ---------------- kernels ----------------

// Fused prep: three independent jobs dispatched by block range.
//  blocks [0, 64):        light table  (sigmoid-normalize + 128-dim contraction)
//  blocks [64, 2112):     density pack (fp32 pair -> half2)
//  blocks [2112, 2160):   accumulator zero
__global__ void __launch_bounds__(256) k_prep(
    const float* __restrict__ lp, const float* __restrict__ li,
    const float* __restrict__ dv)
{
    __shared__ float w[NLIGHT*HDIM];
    __shared__ float red[8];
    int bid = blockIdx.x;
    int t = threadIdx.x;

    if (bid < 64) {
        // ---- light: w = sigmoid(lp)/||sigmoid(lp)||, then per-xz contraction
        float sumsq = 0.0f;
        #pragma unroll
        for (int j = 0; j < 4; j++) {
            int i = t + j * 256;
            float s = 1.0f / (1.0f + expf(-lp[i]));
            w[i] = s;
            sumsq += s * s;
        }
        #pragma unroll
        for (int off = 16; off > 0; off >>= 1)
            sumsq += __shfl_xor_sync(0xFFFFFFFFu, sumsq, off);
        if ((t & 31) == 0) red[t >> 5] = sumsq;
        __syncthreads();
        float inv;
        {
            float tot = red[0];
            #pragma unroll
            for (int k = 1; k < 8; k++) tot += red[k];
            inv = rsqrtf(tot);
        }
        __syncthreads();
        #pragma unroll
        for (int j = 0; j < 4; j++) w[t + j * 256] *= inv;
        __syncthreads();

        int xz = bid * 256 + t;
        float acc[NLIGHT];
        #pragma unroll
        for (int n = 0; n < NLIGHT; n++) acc[n] = 0.0f;
        #pragma unroll 4
        for (int h = 0; h < HDIM; h++) {
            float v = li[h * ROWS_T + xz];
            #pragma unroll
            for (int n = 0; n < NLIGHT; n++)
                acc[n] = fmaf(v, w[n * HDIM + h], acc[n]);
        }
        uint4 packed;
        packed.x = h2_to_u(__floats2half2_rn(acc[0], acc[1]));
        packed.y = h2_to_u(__floats2half2_rn(acc[2], acc[3]));
        packed.z = h2_to_u(__floats2half2_rn(acc[4], acc[5]));
        packed.w = h2_to_u(__floats2half2_rn(acc[6], acc[7]));
        g_lh[xz] = packed;
    } else if (bid < 2112) {
        // ---- density pack: d2h[col] = h2(dv[0][col], dv[1][col])
        int i = ((bid - 64) * 256 + t) * 4;
        float4 a = *reinterpret_cast<const float4*>(dv + i);
        float4 b = *reinterpret_cast<const float4*>(dv + XYZ + i);
        uint4 o;
        o.x = h2_to_u(__floats2half2_rn(a.x, b.x));
        o.y = h2_to_u(__floats2half2_rn(a.y, b.y));
        o.z = h2_to_u(__floats2half2_rn(a.z, b.z));
        o.w = h2_to_u(__floats2half2_rn(a.w, b.w));
        *reinterpret_cast<uint4*>(g_d2h + i) = o;
    } else {
        // ---- zero acc: 48 blocks * 256 threads * 16 float4 = 196608 float4
        float4* av = reinterpret_cast<float4*>(g_acc);
        int base = (bid - 2112) * (256 * 16) + t;
        #pragma unroll
        for (int j = 0; j < 16; j++)
            av[base + j * 256] = make_float4(0.f, 0.f, 0.f, 0.f);
    }
}

__device__ __forceinline__ void red_v4(float* p, float a, float b, float c, float d) {
    unsigned long long gp = __cvta_generic_to_global((void*)p);
    asm volatile("red.global.add.v4.f32 [%0], {%1,%2,%3,%4};"
                 :: "l"(gp), "f"(a), "f"(b), "f"(c), "f"(d) : "memory");
}

// scatter: one thread per 4 consecutive nnz (same camera; NNZ % 4 == 0)
__global__ void __launch_bounds__(256) k_scatter(
    const int* __restrict__ rows, const int* __restrict__ cols,
    const float* __restrict__ vals)
{
    int t = blockIdx.x * 256 + threadIdx.x;     // 0 .. 3*NNZ/4-1
    int cam = t >> 19;                           // NNZ/4 = 2^19 per camera

    // read-once streams: evict-first so they don't displace the gather tables
    int4   r4 = __ldcs(reinterpret_cast<const int4*>(rows) + t);
    int4   c4 = __ldcs(reinterpret_cast<const int4*>(cols) + t);
    float4 v4 = __ldcs(reinterpret_cast<const float4*>(vals) + t);

    int rr[4] = {r4.x, r4.y, r4.z, r4.w};
    int cc[4] = {c4.x, c4.y, c4.z, c4.w};
    float vv[4] = {v4.x, v4.y, v4.z, v4.w};

    // d2 gather: L2-only (.cg) — 8MB table, L2-resident
    unsigned dh[4];
    #pragma unroll
    for (int j = 0; j < 4; j++) dh[j] = __ldcg(&g_d2h[cc[j]]);

    // light gather: L1-cached (.ca) — 256KB table, mostly L1-resident
    uint4 l[4];
    #pragma unroll
    for (int j = 0; j < 4; j++) {
        int xz = ((cc[j] >> 14) << 7) | (cc[j] & 127);
        l[j] = __ldg(&g_lh[xz]);
    }

    float* cbase = g_acc + ((unsigned)cam << 18);   // cam * 16384 * 16
    #pragma unroll
    for (int j = 0; j < 4; j++) {
        float2 d = __half22float2(u_to_h2(dh[j]));
        float a = vv[j] * d.x;
        float b = vv[j] * d.y;
        float2 l01 = __half22float2(u_to_h2(l[j].x));
        float2 l23 = __half22float2(u_to_h2(l[j].y));
        float2 l45 = __half22float2(u_to_h2(l[j].z));
        float2 l67 = __half22float2(u_to_h2(l[j].w));
        float* base = cbase + ((unsigned)rr[j] << 4);
        red_v4(base + 0,  a*l01.x, a*l01.y, a*l23.x, a*l23.y);
        red_v4(base + 4,  a*l45.x, a*l45.y, a*l67.x, a*l67.y);
        red_v4(base + 8,  b*l01.x, b*l01.y, b*l23.x, b*l23.y);
        red_v4(base + 12, b*l45.x, b*l45.y, b*l67.x, b*l67.y);
    }
}

// finalize: out[b,n,c,X,Y] = acc[c][X*128+Y][b*8+n] * (1 + noise[i])
__global__ void __launch_bounds__(256) k_final(
    float* __restrict__ out,
    unsigned kn0, unsigned kn1, unsigned ke0, unsigned ke1)
{
    int i = blockIdx.x * 256 + threadIdx.x;   // 0 .. OUTSZ-1
    int r  = i & (ROWS_T - 1);
    int t  = i >> 14;          // bn*3 + c
    int bn = t / NCAM;
    int c  = t - bn * NCAM;

    float x = g_acc[((((unsigned)c << 14) + (unsigned)r) << 4) + (unsigned)bn];

    // normal(kn): uniform in [nextafter(-1,0), 1), z = sqrt(2)*erfinv(u)
    unsigned nb = tf_bits_part(kn0, kn1, (unsigned)i);
    float fn = __uint_as_float((nb >> 9) | 0x3f800000u) - 1.0f;
    const float lo = -0.99999994f;                 // nextafterf(-1,0)
    float u = fmaxf(lo, fn * (1.0f - lo) + lo);
    float nrm = 1.41421356237309515f * erfinvf(u);

    // exponential(ke): u in [0,1), e = -log1p(-u)
    unsigned eb = tf_bits_part(ke0, ke1, (unsigned)i);
    float fe = __uint_as_float((eb >> 9) | 0x3f800000u) - 1.0f;
    float ex = -log1pf(-fe);

    float noise = (P_LOC + P_SCALE * nrm) + (P_K * P_SCALE) * ex;
    out[i] = x + x * noise;
}

// ---------------- launch ----------------
extern "C" void kernel_launch(void* const* d_in, const int* in_sizes, int n_in,
                              void* d_out, int out_size)
{
    const float* density    = (const float*)d_in[0];  // (2,128,128,128)
    const float* light_pat  = (const float*)d_in[1];  // (8,128)
    const float* light_info = (const float*)d_in[2];  // (128,128,128)
    const int*   ray_rows   = (const int*)d_in[3];    // (3, NNZ)
    const int*   ray_cols   = (const int*)d_in[4];    // (3, NNZ)
    const float* ray_vals   = (const float*)d_in[5];  // (3, NNZ)
    float* out = (float*)d_out;

    // jax.random.key(42); partitionable split(key,2): subkey_i = threefry(k,(0,i))
    unsigned kn0, kn1, ke0, ke1;
    threefry2x32(0u, 42u, 0u, 0u, &kn0, &kn1);   // subkey 0 -> normal
    threefry2x32(0u, 42u, 0u, 1u, &ke0, &ke1);   // subkey 1 -> exponential

    k_prep<<<2160, 256>>>(light_pat, light_info, density);
    k_scatter<<<(NCAM*NNZ/4)/256, 256>>>(ray_rows, ray_cols, ray_vals);
    k_final<<<OUTSZ/256, 256>>>(out, kn0, kn1, ke0, ke1);
}

// round 16
// speedup vs baseline: 1.1389x; 1.0559x over previous
#include <cuda_runtime.h>
#include <cuda_fp16.h>
#include <cstdint>

// Problem constants (fixed shapes)
#define BATCH   2
#define NLIGHT  8
#define HDIM    128
#define D0      128
#define D1      128
#define D2      128
#define NCAM    3
#define NNZ     2097152              // 2^21
#define XYZ     (D0*D1*D2)           // 2^21
#define ROWS_T  (D0*D1)              // 16384
#define BN      (BATCH*NLIGHT)       // 16
#define OUTSZ   (BATCH*NLIGHT*NCAM*D0*D1)  // 786432

// exponnorm params
#define P_K     1.790987517302874f
#define P_LOC   -0.08208043639065216f
#define P_SCALE 0.05720079131427573f

// ---------------- bit-cast helpers ----------------
__device__ __forceinline__ unsigned h2_to_u(half2 h) {
    __half2_raw r = *reinterpret_cast<__half2_raw*>(&h);
    return (unsigned)r.x | ((unsigned)r.y << 16);
}
__device__ __forceinline__ half2 u_to_h2(unsigned u) {
    __half2_raw r;
    r.x = (unsigned short)(u & 0xFFFFu);
    r.y = (unsigned short)(u >> 16);
    return *reinterpret_cast<half2*>(&r);
}

// ---------------- device scratch (static, no allocations) ----------------
__device__ uint4    g_lh[ROWS_T];            // light[xz] as 8 x fp16, 256KB
__device__ unsigned g_d2h[XYZ];              // density (d0,d1) as half2, 8MB
__device__ float    g_acc[NCAM*ROWS_T*BN];   // accumulator [c][row][bn], 3MB

// ---------------- threefry2x32 ----------------
__host__ __device__ __forceinline__ unsigned rotl32(unsigned x, int r) {
    return (x << r) | (x >> (32 - r));
}

__host__ __device__ __forceinline__ void threefry2x32(
    unsigned k0, unsigned k1, unsigned x0, unsigned x1,
    unsigned* o0, unsigned* o1)
{
    unsigned ks0 = k0, ks1 = k1, ks2 = k0 ^ k1 ^ 0x1BD11BDAu;
    x0 += ks0; x1 += ks1;
#define TF_R4(a,b,c,d) \
    x0 += x1; x1 = rotl32(x1,a); x1 ^= x0; \
    x0 += x1; x1 = rotl32(x1,b); x1 ^= x0; \
    x0 += x1; x1 = rotl32(x1,c); x1 ^= x0; \
    x0 += x1; x1 = rotl32(x1,d); x1 ^= x0;
    TF_R4(13,15,26,6);  x0 += ks1; x1 += ks2 + 1u;
    TF_R4(17,29,16,24); x0 += ks2; x1 += ks0 + 2u;
    TF_R4(13,15,26,6);  x0 += ks0; x1 += ks1 + 3u;
    TF_R4(17,29,16,24); x0 += ks1; x1 += ks2 + 4u;
    TF_R4(13,15,26,6);  x0 += ks2; x1 += ks0 + 5u;
#undef TF_R4
    *o0 = x0; *o1 = x1;
}

// Partitionable threefry random_bits: element i -> counter (0, i), out0 ^ out1.
__device__ __forceinline__ unsigned tf_bits_part(unsigned k0, unsigned k1, unsigned i) {
    unsigned o0, o1;
    threefry2x32(k0, k1, 0u, i, &o0, &o1);
    return o0 ^ o1;
}

// ---------------- kernels ----------------

// Fused prep: three independent jobs dispatched by block range.
//  blocks [0, 256):       light table — 64 xz per block, h-loop split 4-way
//  blocks [256, 2304):    density pack (fp32 pair -> half2)
//  blocks [2304, 2352):   accumulator zero
__global__ void __launch_bounds__(256) k_prep(
    const float* __restrict__ lp, const float* __restrict__ li,
    const float* __restrict__ dv)
{
    __shared__ float w[NLIGHT*HDIM];      // 4KB
    __shared__ float red[8];
    __shared__ float sp[4*64*NLIGHT];     // 8KB partials [q][xz][n]
    int bid = blockIdx.x;
    int t = threadIdx.x;

    if (bid < 256) {
        // ---- light: w = sigmoid(lp)/||sigmoid(lp)|| (redundant per block)
        float sumsq = 0.0f;
        #pragma unroll
        for (int j = 0; j < 4; j++) {
            int i = t + j * 256;
            float s = 1.0f / (1.0f + expf(-lp[i]));
            w[i] = s;
            sumsq += s * s;
        }
        #pragma unroll
        for (int off = 16; off > 0; off >>= 1)
            sumsq += __shfl_xor_sync(0xFFFFFFFFu, sumsq, off);
        if ((t & 31) == 0) red[t >> 5] = sumsq;
        __syncthreads();
        float inv;
        {
            float tot = red[0];
            #pragma unroll
            for (int k = 1; k < 8; k++) tot += red[k];
            inv = rsqrtf(tot);
        }
        __syncthreads();
        #pragma unroll
        for (int j = 0; j < 4; j++) w[t + j * 256] *= inv;
        __syncthreads();

        // ---- contraction: thread t handles xz = bid*64 + (t&63), h in [32q, 32q+32)
        int xl = t & 63;
        int q  = t >> 6;
        int xz = (bid << 6) + xl;
        int h0 = q << 5;
        float acc[NLIGHT];
        #pragma unroll
        for (int n = 0; n < NLIGHT; n++) acc[n] = 0.0f;
        #pragma unroll 8
        for (int hh = 0; hh < 32; hh++) {
            float v = li[(h0 + hh) * ROWS_T + xz];
            #pragma unroll
            for (int n = 0; n < NLIGHT; n++)
                acc[n] = fmaf(v, w[n * HDIM + h0 + hh], acc[n]);
        }
        float* spp = &sp[(q * 64 + xl) * NLIGHT];
        #pragma unroll
        for (int n = 0; n < NLIGHT; n++) spp[n] = acc[n];
        __syncthreads();

        if (t < 64) {
            float s[NLIGHT];
            #pragma unroll
            for (int n = 0; n < NLIGHT; n++) s[n] = 0.0f;
            #pragma unroll
            for (int q2 = 0; q2 < 4; q2++) {
                const float* p = &sp[(q2 * 64 + t) * NLIGHT];
                #pragma unroll
                for (int n = 0; n < NLIGHT; n++) s[n] += p[n];
            }
            uint4 packed;
            packed.x = h2_to_u(__floats2half2_rn(s[0], s[1]));
            packed.y = h2_to_u(__floats2half2_rn(s[2], s[3]));
            packed.z = h2_to_u(__floats2half2_rn(s[4], s[5]));
            packed.w = h2_to_u(__floats2half2_rn(s[6], s[7]));
            g_lh[(bid << 6) + t] = packed;
        }
    } else if (bid < 2304) {
        // ---- density pack: d2h[col] = h2(dv[0][col], dv[1][col])
        int i = ((bid - 256) * 256 + t) * 4;
        float4 a = *reinterpret_cast<const float4*>(dv + i);
        float4 b = *reinterpret_cast<const float4*>(dv + XYZ + i);
        uint4 o;
        o.x = h2_to_u(__floats2half2_rn(a.x, b.x));
        o.y = h2_to_u(__floats2half2_rn(a.y, b.y));
        o.z = h2_to_u(__floats2half2_rn(a.z, b.z));
        o.w = h2_to_u(__floats2half2_rn(a.w, b.w));
        *reinterpret_cast<uint4*>(g_d2h + i) = o;
    } else {
        // ---- zero acc: 48 blocks * 256 threads * 16 float4 = 196608 float4
        float4* av = reinterpret_cast<float4*>(g_acc);
        int base = (bid - 2304) * (256 * 16) + t;
        #pragma unroll
        for (int j = 0; j < 16; j++)
            av[base + j * 256] = make_float4(0.f, 0.f, 0.f, 0.f);
    }
}

__device__ __forceinline__ void red_v4(float* p, float a, float b, float c, float d) {
    unsigned long long gp = __cvta_generic_to_global((void*)p);
    asm volatile("red.global.add.v4.f32 [%0], {%1,%2,%3,%4};"
                 :: "l"(gp), "f"(a), "f"(b), "f"(c), "f"(d) : "memory");
}

// scatter: one thread per 4 consecutive nnz (same camera; NNZ % 4 == 0)
__global__ void __launch_bounds__(256) k_scatter(
    const int* __restrict__ rows, const int* __restrict__ cols,
    const float* __restrict__ vals)
{
    int t = blockIdx.x * 256 + threadIdx.x;     // 0 .. 3*NNZ/4-1
    int cam = t >> 19;                           // NNZ/4 = 2^19 per camera

    // read-once streams: evict-first so they don't displace the gather tables
    int4   r4 = __ldcs(reinterpret_cast<const int4*>(rows) + t);
    int4   c4 = __ldcs(reinterpret_cast<const int4*>(cols) + t);
    float4 v4 = __ldcs(reinterpret_cast<const float4*>(vals) + t);

    int rr[4] = {r4.x, r4.y, r4.z, r4.w};
    int cc[4] = {c4.x, c4.y, c4.z, c4.w};
    float vv[4] = {v4.x, v4.y, v4.z, v4.w};

    // d2 gather: L2-only (.cg) — 8MB table, L2-resident
    unsigned dh[4];
    #pragma unroll
    for (int j = 0; j < 4; j++) dh[j] = __ldcg(&g_d2h[cc[j]]);

    // light gather: L1-cached (.ca) — 256KB table, mostly L1-resident
    uint4 l[4];
    #pragma unroll
    for (int j = 0; j < 4; j++) {
        int xz = ((cc[j] >> 14) << 7) | (cc[j] & 127);
        l[j] = __ldg(&g_lh[xz]);
    }

    float* cbase = g_acc + ((unsigned)cam << 18);   // cam * 16384 * 16
    #pragma unroll
    for (int j = 0; j < 4; j++) {
        float2 d = __half22float2(u_to_h2(dh[j]));
        float a = vv[j] * d.x;
        float b = vv[j] * d.y;
        float2 l01 = __half22float2(u_to_h2(l[j].x));
        float2 l23 = __half22float2(u_to_h2(l[j].y));
        float2 l45 = __half22float2(u_to_h2(l[j].z));
        float2 l67 = __half22float2(u_to_h2(l[j].w));
        float* base = cbase + ((unsigned)rr[j] << 4);
        red_v4(base + 0,  a*l01.x, a*l01.y, a*l23.x, a*l23.y);
        red_v4(base + 4,  a*l45.x, a*l45.y, a*l67.x, a*l67.y);
        red_v4(base + 8,  b*l01.x, b*l01.y, b*l23.x, b*l23.y);
        red_v4(base + 12, b*l45.x, b*l45.y, b*l67.x, b*l67.y);
    }
}

// finalize: out[b,n,c,X,Y] = acc[c][X*128+Y][b*8+n] * (1 + noise[i])
__global__ void __launch_bounds__(256) k_final(
    float* __restrict__ out,
    unsigned kn0, unsigned kn1, unsigned ke0, unsigned ke1)
{
    int i = blockIdx.x * 256 + threadIdx.x;   // 0 .. OUTSZ-1
    int r  = i & (ROWS_T - 1);
    int t  = i >> 14;          // bn*3 + c
    int bn = t / NCAM;
    int c  = t - bn * NCAM;

    float x = g_acc[((((unsigned)c << 14) + (unsigned)r) << 4) + (unsigned)bn];

    // normal(kn): uniform in [nextafter(-1,0), 1), z = sqrt(2)*erfinv(u)
    unsigned nb = tf_bits_part(kn0, kn1, (unsigned)i);
    float fn = __uint_as_float((nb >> 9) | 0x3f800000u) - 1.0f;
    const float lo = -0.99999994f;                 // nextafterf(-1,0)
    float u = fmaxf(lo, fn * (1.0f - lo) + lo);
    float nrm = 1.41421356237309515f * erfinvf(u);

    // exponential(ke): u in [0,1), e = -log1p(-u)
    unsigned eb = tf_bits_part(ke0, ke1, (unsigned)i);
    float fe = __uint_as_float((eb >> 9) | 0x3f800000u) - 1.0f;
    float ex = -log1pf(-fe);

    float noise = (P_LOC + P_SCALE * nrm) + (P_K * P_SCALE) * ex;
    out[i] = x + x * noise;
}

// ---------------- launch ----------------
extern "C" void kernel_launch(void* const* d_in, const int* in_sizes, int n_in,
                              void* d_out, int out_size)
{
    const float* density    = (const float*)d_in[0];  // (2,128,128,128)
    const float* light_pat  = (const float*)d_in[1];  // (8,128)
    const float* light_info = (const float*)d_in[2];  // (128,128,128)
    const int*   ray_rows   = (const int*)d_in[3];    // (3, NNZ)
    const int*   ray_cols   = (const int*)d_in[4];    // (3, NNZ)
    const float* ray_vals   = (const float*)d_in[5];  // (3, NNZ)
    float* out = (float*)d_out;

    // jax.random.key(42); partitionable split(key,2): subkey_i = threefry(k,(0,i))
    unsigned kn0, kn1, ke0, ke1;
    threefry2x32(0u, 42u, 0u, 0u, &kn0, &kn1);   // subkey 0 -> normal
    threefry2x32(0u, 42u, 0u, 1u, &ke0, &ke1);   // subkey 1 -> exponential

    k_prep<<<2352, 256>>>(light_pat, light_info, density);
    k_scatter<<<(NCAM*NNZ/4)/256, 256>>>(ray_rows, ray_cols, ray_vals);
    k_final<<<OUTSZ/256, 256>>>(out, kn0, kn1, ke0, ke1);
}

// round 17
// speedup vs baseline: 1.1427x; 1.0033x over previous
#include <cuda_runtime.h>
#include <cuda_fp16.h>
#include <cstdint>

// Problem constants (fixed shapes)
#define BATCH   2
#define NLIGHT  8
#define HDIM    128
#define D0      128
#define D1      128
#define D2      128
#define NCAM    3
#define NNZ     2097152              // 2^21
#define XYZ     (D0*D1*D2)           // 2^21
#define ROWS_T  (D0*D1)              // 16384
#define BN      (BATCH*NLIGHT)       // 16
#define OUTSZ   (BATCH*NLIGHT*NCAM*D0*D1)  // 786432

// exponnorm params
#define P_K     1.790987517302874f
#define P_LOC   -0.08208043639065216f
#define P_SCALE 0.05720079131427573f

// ---------------- bit-cast helpers ----------------
__device__ __forceinline__ unsigned h2_to_u(half2 h) {
    __half2_raw r = *reinterpret_cast<__half2_raw*>(&h);
    return (unsigned)r.x | ((unsigned)r.y << 16);
}
__device__ __forceinline__ half2 u_to_h2(unsigned u) {
    __half2_raw r;
    r.x = (unsigned short)(u & 0xFFFFu);
    r.y = (unsigned short)(u >> 16);
    return *reinterpret_cast<half2*>(&r);
}

// ---------------- device scratch (static, no allocations) ----------------
__device__ uint4    g_lh[ROWS_T];            // light[xz] as 8 x fp16, 256KB
__device__ unsigned g_d2h[XYZ];              // density (d0,d1) as half2, 8MB
__device__ float    g_acc[NCAM*ROWS_T*BN];   // accumulator [c][row][bn], 3MB
__device__ float    g_noise[OUTSZ];          // 1 + noise[i], 3MB

// ---------------- threefry2x32 ----------------
__host__ __device__ __forceinline__ unsigned rotl32(unsigned x, int r) {
    return (x << r) | (x >> (32 - r));
}

__host__ __device__ __forceinline__ void threefry2x32(
    unsigned k0, unsigned k1, unsigned x0, unsigned x1,
    unsigned* o0, unsigned* o1)
{
    unsigned ks0 = k0, ks1 = k1, ks2 = k0 ^ k1 ^ 0x1BD11BDAu;
    x0 += ks0; x1 += ks1;
#define TF_R4(a,b,c,d) \
    x0 += x1; x1 = rotl32(x1,a); x1 ^= x0; \
    x0 += x1; x1 = rotl32(x1,b); x1 ^= x0; \
    x0 += x1; x1 = rotl32(x1,c); x1 ^= x0; \
    x0 += x1; x1 = rotl32(x1,d); x1 ^= x0;
    TF_R4(13,15,26,6);  x0 += ks1; x1 += ks2 + 1u;
    TF_R4(17,29,16,24); x0 += ks2; x1 += ks0 + 2u;
    TF_R4(13,15,26,6);  x0 += ks0; x1 += ks1 + 3u;
    TF_R4(17,29,16,24); x0 += ks1; x1 += ks2 + 4u;
    TF_R4(13,15,26,6);  x0 += ks2; x1 += ks0 + 5u;
#undef TF_R4
    *o0 = x0; *o1 = x1;
}

// Partitionable threefry random_bits: element i -> counter (0, i), out0 ^ out1.
__device__ __forceinline__ unsigned tf_bits_part(unsigned k0, unsigned k1, unsigned i) {
    unsigned o0, o1;
    threefry2x32(k0, k1, 0u, i, &o0, &o1);
    return o0 ^ o1;
}

// ---------------- kernels ----------------

// Fused prep: four independent jobs dispatched by block range.
//  blocks [0, 256):       light table — 64 xz per block, h-loop split 4-way
//  blocks [256, 1280):    density pack (fp32 pair -> half2), 2 uint4/thread
//  blocks [1280, 1328):   accumulator zero
//  blocks [1328, 4400):   noise table (threefry -> 1 + exponnorm), 1 elem/thread
__global__ void __launch_bounds__(256) k_prep(
    const float* __restrict__ lp, const float* __restrict__ li,
    const float* __restrict__ dv,
    unsigned kn0, unsigned kn1, unsigned ke0, unsigned ke1)
{
    __shared__ float w[NLIGHT*HDIM];      // 4KB
    __shared__ float red[8];
    __shared__ float sp[4*64*NLIGHT];     // 8KB partials [q][xz][n]
    int bid = blockIdx.x;
    int t = threadIdx.x;

    if (bid < 256) {
        // ---- light: w = sigmoid(lp)/||sigmoid(lp)|| (redundant per block)
        float sumsq = 0.0f;
        #pragma unroll
        for (int j = 0; j < 4; j++) {
            int i = t + j * 256;
            float s = 1.0f / (1.0f + expf(-lp[i]));
            w[i] = s;
            sumsq += s * s;
        }
        #pragma unroll
        for (int off = 16; off > 0; off >>= 1)
            sumsq += __shfl_xor_sync(0xFFFFFFFFu, sumsq, off);
        if ((t & 31) == 0) red[t >> 5] = sumsq;
        __syncthreads();
        float inv;
        {
            float tot = red[0];
            #pragma unroll
            for (int k = 1; k < 8; k++) tot += red[k];
            inv = rsqrtf(tot);
        }
        __syncthreads();
        #pragma unroll
        for (int j = 0; j < 4; j++) w[t + j * 256] *= inv;
        __syncthreads();

        // ---- contraction: thread t handles xz = bid*64 + (t&63), h in [32q, 32q+32)
        int xl = t & 63;
        int q  = t >> 6;
        int xz = (bid << 6) + xl;
        int h0 = q << 5;
        float acc[NLIGHT];
        #pragma unroll
        for (int n = 0; n < NLIGHT; n++) acc[n] = 0.0f;
        #pragma unroll 8
        for (int hh = 0; hh < 32; hh++) {
            float v = li[(h0 + hh) * ROWS_T + xz];
            #pragma unroll
            for (int n = 0; n < NLIGHT; n++)
                acc[n] = fmaf(v, w[n * HDIM + h0 + hh], acc[n]);
        }
        float* spp = &sp[(q * 64 + xl) * NLIGHT];
        #pragma unroll
        for (int n = 0; n < NLIGHT; n++) spp[n] = acc[n];
        __syncthreads();

        if (t < 64) {
            float s[NLIGHT];
            #pragma unroll
            for (int n = 0; n < NLIGHT; n++) s[n] = 0.0f;
            #pragma unroll
            for (int q2 = 0; q2 < 4; q2++) {
                const float* p = &sp[(q2 * 64 + t) * NLIGHT];
                #pragma unroll
                for (int n = 0; n < NLIGHT; n++) s[n] += p[n];
            }
            uint4 packed;
            packed.x = h2_to_u(__floats2half2_rn(s[0], s[1]));
            packed.y = h2_to_u(__floats2half2_rn(s[2], s[3]));
            packed.z = h2_to_u(__floats2half2_rn(s[4], s[5]));
            packed.w = h2_to_u(__floats2half2_rn(s[6], s[7]));
            g_lh[(bid << 6) + t] = packed;
        }
    } else if (bid < 1280) {
        // ---- density pack: 2 uint4 per thread (8 cols), batched loads for MLP
        int i = ((bid - 256) * 256 + t) * 8;
        float4 a0 = *reinterpret_cast<const float4*>(dv + i);
        float4 a1 = *reinterpret_cast<const float4*>(dv + i + 4);
        float4 b0 = *reinterpret_cast<const float4*>(dv + XYZ + i);
        float4 b1 = *reinterpret_cast<const float4*>(dv + XYZ + i + 4);
        uint4 o0, o1;
        o0.x = h2_to_u(__floats2half2_rn(a0.x, b0.x));
        o0.y = h2_to_u(__floats2half2_rn(a0.y, b0.y));
        o0.z = h2_to_u(__floats2half2_rn(a0.z, b0.z));
        o0.w = h2_to_u(__floats2half2_rn(a0.w, b0.w));
        o1.x = h2_to_u(__floats2half2_rn(a1.x, b1.x));
        o1.y = h2_to_u(__floats2half2_rn(a1.y, b1.y));
        o1.z = h2_to_u(__floats2half2_rn(a1.z, b1.z));
        o1.w = h2_to_u(__floats2half2_rn(a1.w, b1.w));
        *reinterpret_cast<uint4*>(g_d2h + i) = o0;
        *reinterpret_cast<uint4*>(g_d2h + i + 4) = o1;
    } else if (bid < 1328) {
        // ---- zero acc: 48 blocks * 256 threads * 16 float4 = 196608 float4
        float4* av = reinterpret_cast<float4*>(g_acc);
        int base = (bid - 1280) * (256 * 16) + t;
        #pragma unroll
        for (int j = 0; j < 16; j++)
            av[base + j * 256] = make_float4(0.f, 0.f, 0.f, 0.f);
    } else {
        // ---- noise table: g_noise[i] = 1 + exponnorm noise (input-independent)
        int i = (bid - 1328) * 256 + t;      // 0 .. OUTSZ-1

        unsigned nb = tf_bits_part(kn0, kn1, (unsigned)i);
        float fn = __uint_as_float((nb >> 9) | 0x3f800000u) - 1.0f;
        const float lo = -0.99999994f;               // nextafterf(-1,0)
        float u = fmaxf(lo, fn * (1.0f - lo) + lo);
        float nrm = 1.41421356237309515f * erfinvf(u);

        unsigned eb = tf_bits_part(ke0, ke1, (unsigned)i);
        float fe = __uint_as_float((eb >> 9) | 0x3f800000u) - 1.0f;
        float ex = -log1pf(-fe);

        g_noise[i] = 1.0f + (P_LOC + P_SCALE * nrm) + (P_K * P_SCALE) * ex;
    }
}

__device__ __forceinline__ void red_v4(float* p, float a, float b, float c, float d) {
    unsigned long long gp = __cvta_generic_to_global((void*)p);
    asm volatile("red.global.add.v4.f32 [%0], {%1,%2,%3,%4};"
                 :: "l"(gp), "f"(a), "f"(b), "f"(c), "f"(d) : "memory");
}

// scatter: one thread per 4 consecutive nnz (same camera; NNZ % 4 == 0)
__global__ void __launch_bounds__(256) k_scatter(
    const int* __restrict__ rows, const int* __restrict__ cols,
    const float* __restrict__ vals)
{
    int t = blockIdx.x * 256 + threadIdx.x;     // 0 .. 3*NNZ/4-1
    int cam = t >> 19;                           // NNZ/4 = 2^19 per camera

    // read-once streams: evict-first so they don't displace the gather tables
    int4   r4 = __ldcs(reinterpret_cast<const int4*>(rows) + t);
    int4   c4 = __ldcs(reinterpret_cast<const int4*>(cols) + t);
    float4 v4 = __ldcs(reinterpret_cast<const float4*>(vals) + t);

    int rr[4] = {r4.x, r4.y, r4.z, r4.w};
    int cc[4] = {c4.x, c4.y, c4.z, c4.w};
    float vv[4] = {v4.x, v4.y, v4.z, v4.w};

    // d2 gather: L2-only (.cg) — 8MB table, L2-resident
    unsigned dh[4];
    #pragma unroll
    for (int j = 0; j < 4; j++) dh[j] = __ldcg(&g_d2h[cc[j]]);

    // light gather: L1-cached (.ca) — 256KB table, mostly L1-resident
    uint4 l[4];
    #pragma unroll
    for (int j = 0; j < 4; j++) {
        int xz = ((cc[j] >> 14) << 7) | (cc[j] & 127);
        l[j] = __ldg(&g_lh[xz]);
    }

    float* cbase = g_acc + ((unsigned)cam << 18);   // cam * 16384 * 16
    #pragma unroll
    for (int j = 0; j < 4; j++) {
        float2 d = __half22float2(u_to_h2(dh[j]));
        float a = vv[j] * d.x;
        float b = vv[j] * d.y;
        float2 l01 = __half22float2(u_to_h2(l[j].x));
        float2 l23 = __half22float2(u_to_h2(l[j].y));
        float2 l45 = __half22float2(u_to_h2(l[j].z));
        float2 l67 = __half22float2(u_to_h2(l[j].w));
        float* base = cbase + ((unsigned)rr[j] << 4);
        red_v4(base + 0,  a*l01.x, a*l01.y, a*l23.x, a*l23.y);
        red_v4(base + 4,  a*l45.x, a*l45.y, a*l67.x, a*l67.y);
        red_v4(base + 8,  b*l01.x, b*l01.y, b*l23.x, b*l23.y);
        red_v4(base + 12, b*l45.x, b*l45.y, b*l67.x, b*l67.y);
    }
}

// finalize: out[b,n,c,X,Y] = acc[c][X*128+Y][b*8+n] * noisef[i]  (pure memory)
__global__ void __launch_bounds__(256) k_final(float* __restrict__ out) {
    int i = blockIdx.x * 256 + threadIdx.x;   // 0 .. OUTSZ-1
    int r  = i & (ROWS_T - 1);
    int t  = i >> 14;          // bn*3 + c
    int bn = t / NCAM;
    int c  = t - bn * NCAM;

    float x = g_acc[((((unsigned)c << 14) + (unsigned)r) << 4) + (unsigned)bn];
    out[i] = x * g_noise[i];
}

// ---------------- launch ----------------
extern "C" void kernel_launch(void* const* d_in, const int* in_sizes, int n_in,
                              void* d_out, int out_size)
{
    const float* density    = (const float*)d_in[0];  // (2,128,128,128)
    const float* light_pat  = (const float*)d_in[1];  // (8,128)
    const float* light_info = (const float*)d_in[2];  // (128,128,128)
    const int*   ray_rows   = (const int*)d_in[3];    // (3, NNZ)
    const int*   ray_cols   = (const int*)d_in[4];    // (3, NNZ)
    const float* ray_vals   = (const float*)d_in[5];  // (3, NNZ)
    float* out = (float*)d_out;

    // jax.random.key(42); partitionable split(key,2): subkey_i = threefry(k,(0,i))
    unsigned kn0, kn1, ke0, ke1;
    threefry2x32(0u, 42u, 0u, 0u, &kn0, &kn1);   // subkey 0 -> normal
    threefry2x32(0u, 42u, 0u, 1u, &ke0, &ke1);   // subkey 1 -> exponential

    k_prep<<<1328 + OUTSZ/256, 256>>>(light_pat, light_info, density,
                                      kn0, kn1, ke0, ke1);
    k_scatter<<<(NCAM*NNZ/4)/256, 256>>>(ray_rows, ray_cols, ray_vals);
    k_final<<<OUTSZ/256, 256>>>(out);
}